// round 15
// baseline (speedup 1.0000x reference)
#include <cuda_runtime.h>
#include <cuda_bf16.h>

#define Bc 8
#define Nmax 34000
#define Mc 64
#define EPSL 1e-7f
#define FULLM 0xFFFFFFFFu
#define FCH 256         // anchors per fused block (1 per thread)
#define NCH 48          // reduce chunks per batch
#define SENT 0x8000000000000000ull   // key of +0.0 in high 32; only ciou>0 beats it

// Scratch (static device globals; zero-initialized at load; no allocation allowed)
__device__ float4       g_pb[Bc * Nmax];
__device__ float        g_at1[Bc * Nmax];
__device__ unsigned int g_it[Bc * Nmax];
__device__ float        g_part2[Bc * NCH * 3];
__device__ unsigned int g_cnt;                            // re-zeroed by k_reduce epilogue
__device__ unsigned int g_cnt_m[Bc * Mc];                 // re-zeroed by k_reduce epilogue
__device__ unsigned int g_list[(size_t)Bc * Mc * Nmax];   // survivor anchor indices

// ---------------------------------------------------------------------------
// Fused kernel: DFL decode (1 anchor/thread, scalar coalesced loads,
// NO register-array batching -- it spilled to local memory in R14) +
// mask-screen filter. Grid (ceil(N/FCH), Bc) ~ 1064 blocks.
// Requires g_cnt_m zeroed on entry (k_reduce epilogue / static init).
// ---------------------------------------------------------------------------
__global__ __launch_bounds__(256) void k_dfil(const float* __restrict__ boxes,
                                              const float* __restrict__ targets, int N) {
    const int b   = blockIdx.y;
    const int c0  = blockIdx.x * FCH;
    const int tid = threadIdx.x;
    const int w   = tid >> 5;

    __shared__ float4 s_t[Mc];
    __shared__ unsigned long long s_mx[16], s_my[16];
    __shared__ int s_wc[8][Mc];    // per-warp counts, then cursors
    __shared__ int s_wb[8][Mc];    // per-warp bases (exclusive prefix)
    __shared__ int s_base[Mc];     // global base per m

    for (int i = tid; i < 8 * Mc; i += 256) s_wc[i >> 6][i & 63] = 0;
    if (tid < 16) { s_mx[tid] = 0ull; s_my[tid] = 0ull; }
    __syncthreads();
    if (tid < Mc) {
        const float* t = targets + ((size_t)b * Mc + tid) * 4;
        float4 tv = make_float4(t[0], t[1], t[2], t[3]);
        s_t[tid] = tv;
        int cx0 = min(max((int)floorf(tv.x), 0), 15);
        int cx1 = min(max((int)floorf(tv.z), 0), 15);
        int cy0 = min(max((int)floorf(tv.y), 0), 15);
        int cy1 = min(max((int)floorf(tv.w), 0), 15);
        unsigned long long bit = 1ull << tid;
        for (int c = cx0; c <= cx1; c++) atomicOr(&s_mx[c], bit);
        for (int c = cy0; c <= cy1; c++) atomicOr(&s_my[c], bit);
    }

    // ---- decode one anchor (direct load->exp->accumulate; R2-proven) ----
    const int n = c0 + tid;
    float4 p = make_float4(0.f, 0.f, 0.f, 0.f);
    bool valid = false;

    if (n < N) {
        const float* base = boxes + (size_t)b * 64 * N + n;
        float pb4[4];
#pragma unroll
        for (int k = 0; k < 4; k++) {
            float s = 0.f, e = 0.f;
#pragma unroll
            for (int r = 0; r < 16; r++) {
                float t = __expf(base[(size_t)(k * 16 + r) * N]);
                s += t; e += t * (float)r;
            }
            pb4[k] = __fdividef(e, s);
        }
        p = make_float4(pb4[0], pb4[1], pb4[2], pb4[3]);
        size_t o = (size_t)b * N + n;
        g_pb[o]  = p;
        g_at1[o] = atanf(__fdividef(p.z - p.x, p.w - p.y + EPSL));
        g_it[o]  = 0u;
        valid = (p.z > p.x) && (p.w > p.y);
    }
    __syncthreads();   // masks + s_t ready; s_wc zeroed

    // ---- Pass A: screen + count (fire-and-forget smem atomics) ----
    unsigned long long msk = 0ull;
    if (valid) {
        int cx0 = min(max((int)floorf(p.x), 0), 15);
        int cx1 = min(max((int)floorf(p.z), 0), 15);
        int cy0 = min(max((int)floorf(p.y), 0), 15);
        int cy1 = min(max((int)floorf(p.w), 0), 15);
        unsigned long long mx = 0ull, my = 0ull;
        for (int c = cx0; c <= cx1; c++) mx |= s_mx[c];
        for (int c = cy0; c <= cy1; c++) my |= s_my[c];
        unsigned long long cand = mx & my;
        while (cand) {
            int m = __ffsll((long long)cand) - 1;
            cand &= cand - 1;
            float4 t = s_t[m];
            float iw = fminf(p.z, t.z) - fmaxf(p.x, t.x);
            float ih = fminf(p.w, t.w) - fmaxf(p.y, t.y);
            if (iw > 0.f && ih > 0.f) {
                msk |= 1ull << m;
                atomicAdd(&s_wc[w][m], 1);
            }
        }
    }
    __syncthreads();

    // One concurrent batch of global reservations + per-warp prefix bases
    if (tid < Mc) {
        int tot = 0;
#pragma unroll
        for (int ww = 0; ww < 8; ww++) { s_wb[ww][tid] = tot; tot += s_wc[ww][tid]; }
        s_base[tid] = tot ? (int)atomicAdd(&g_cnt_m[b * Mc + tid], (unsigned)tot) : 0;
#pragma unroll
        for (int ww = 0; ww < 8; ww++) s_wc[ww][tid] = 0;   // reset as cursors
    }
    __syncthreads();

    // Pass B: assign slots via per-warp cursors, write indices
    {
        unsigned long long tmp = msk;
        while (tmp) {
            int m = __ffsll((long long)tmp) - 1;
            tmp &= tmp - 1;
            int pos = s_base[m] + s_wb[w][m] + atomicAdd(&s_wc[w][m], 1);
            g_list[(size_t)(b * Mc + m) * Nmax + pos] = (unsigned)n;
        }
    }
}

// ---------------------------------------------------------------------------
// k_ciou: per-(b,m) exact top-10 ciou over the survivor list.
// Sentinel init => insertion only for ciou > 0 (reference keeps topv > 0).
// Extraction: sorted per-thread lists, register offers, shuffle argmax.
// ---------------------------------------------------------------------------
__global__ __launch_bounds__(256) void k_ciou(const float* __restrict__ targets, int N) {
    const int m = blockIdx.x;
    const int b = blockIdx.y;
    const int bm = b * Mc + m;
    const int tid  = threadIdx.x;
    const int lane = tid & 31;
    const int wid  = tid >> 5;

    const float* t = targets + (size_t)bm * 4;
    const float x21 = t[0], y21 = t[1], x22 = t[2], y22 = t[3];
    const float w2 = x22 - x21, h2 = y22 - y21;
    const float area2 = w2 * h2;
    const float at2 = atanf(__fdividef(w2, h2 + EPSL));
    const float sx = x21 + x22, sy = y21 + y22;
    const float VP = 4.0f / (float)(M_PI * M_PI);

    unsigned cnt = g_cnt_m[bm];
    if (cnt > (unsigned)N) cnt = (unsigned)N;

    unsigned long long top[10];
#pragma unroll
    for (int j = 0; j < 10; j++) top[j] = SENT;

    const float4* __restrict__ pb = g_pb + (size_t)b * N;
    const float*  __restrict__ a1 = g_at1 + (size_t)b * N;
    const unsigned* __restrict__ lst = g_list + (size_t)bm * Nmax;

#pragma unroll 4
    for (unsigned i = tid; i < cnt; i += 256) {
        unsigned n = lst[i];
        float4 p = pb[n];
        float at1 = a1[n];
        float w1 = p.z - p.x, h1 = p.w - p.y;

        float iw = fminf(p.z, x22) - fmaxf(p.x, x21); iw = fmaxf(iw, 0.f);
        float ih = fminf(p.w, y22) - fmaxf(p.y, y21); ih = fmaxf(ih, 0.f);
        float inter = iw * ih;
        float uni = w1 * h1 + area2 - inter + EPSL;
        float iou = __fdividef(inter, uni);

        float cw = fmaxf(p.z, x22) - fminf(p.x, x21);
        float ch = fmaxf(p.w, y22) - fminf(p.y, y21);
        float c2 = cw * cw + ch * ch + EPSL;

        float dx = sx - p.x - p.z;
        float dy = sy - p.y - p.w;
        float rho2 = (dx * dx + dy * dy) * 0.25f;

        float d = at2 - at1;
        float v = VP * d * d;
        float av = __fdividef(v * v, v - iou + 1.0f + EPSL);
        float ciou = iou - __fdividef(rho2, c2) - av;

        unsigned u = __float_as_uint(ciou);
        unsigned key = (u & 0x80000000u) ? ~u : (u | 0x80000000u);
        unsigned long long pk =
            ((unsigned long long)key << 32) | (unsigned long long)(0xFFFFFFFFu - n);

        if (pk > top[9]) {   // only ciou > 0 passes (sentinel = +0.0 key)
#pragma unroll
            for (int j = 0; j < 10; j++) {
                if (pk > top[j]) { unsigned long long tmp = top[j]; top[j] = pk; pk = tmp; }
            }
        }
    }

    __shared__ unsigned long long s_w[8];
    __shared__ int                s_wt[8];
    __shared__ unsigned long long s_best;
    __shared__ int                s_btid;

    unsigned long long offer = top[0];

    for (int round = 0; round < 10; ++round) {
        unsigned long long mx = offer; int mt = tid;
#pragma unroll
        for (int off = 16; off > 0; off >>= 1) {
            unsigned long long ov = __shfl_down_sync(FULLM, mx, off);
            int ot = __shfl_down_sync(FULLM, mt, off);
            if (ov > mx) { mx = ov; mt = ot; }
        }
        if (lane == 0) { s_w[wid] = mx; s_wt[wid] = mt; }
        __syncthreads();
        if (wid == 0) {
            unsigned long long v2 = (lane < 8) ? s_w[lane] : 0ull;
            int t2 = (lane < 8) ? s_wt[lane] : 0;
#pragma unroll
            for (int off = 4; off > 0; off >>= 1) {
                unsigned long long ov = __shfl_down_sync(FULLM, v2, off);
                int ot = __shfl_down_sync(FULLM, t2, off);
                if (ov > v2) { v2 = ov; t2 = ot; }
            }
            if (lane == 0) { s_best = v2; s_btid = t2; }
        }
        __syncthreads();
        unsigned long long best = s_best;
        if ((unsigned)(best >> 32) <= 0x80000000u) break;  // value <= 0: done

        if (tid == 0) {
            unsigned n = 0xFFFFFFFFu - (unsigned)(best & 0xFFFFFFFFull);
            atomicMax(&g_it[(size_t)b * N + n], (unsigned)(best >> 32) ^ 0x80000000u);
        }
        if (tid == s_btid) {
#pragma unroll
            for (int j = 0; j < 9; j++) top[j] = top[j + 1];
            top[9] = SENT;
            offer = top[0];
        }
    }
}

// ---------------------------------------------------------------------------
// k_reduce: parallel per-slice reductions (vectorized when N%4==0), grid
// (NCH, Bc). Last block: deterministic fixed-order combine + re-zero counters.
// ---------------------------------------------------------------------------
__global__ __launch_bounds__(256) void k_reduce(const float* __restrict__ scores, int N,
                                                float* out, int out_size, int aligned) {
    const int c = blockIdx.x;
    const int b = blockIdx.y;
    const int tid = threadIdx.x;

    float np = 0.f, bs = 0.f, bc = 0.f;
    const unsigned int* __restrict__ it = g_it + (size_t)b * N;
    const float* __restrict__ sc = scores + (size_t)b * N;

    if (aligned) {
        const int N4 = N >> 2;
        const int L4 = (N4 + NCH - 1) / NCH;
        const int q1 = min(c * L4 + L4, N4);
        for (int q = c * L4 + tid; q < q1; q += 256) {
            uint4  iv4 = *(const uint4*)(it + q * 4);
            float4 s4  = *(const float4*)(sc + q * 4);
            float iv, s;
#pragma unroll
            for (int j = 0; j < 4; j++) {
                iv = __uint_as_float(j == 0 ? iv4.x : j == 1 ? iv4.y : j == 2 ? iv4.z : iv4.w);
                s  = (j == 0 ? s4.x : j == 1 ? s4.y : j == 2 ? s4.z : s4.w);
                if (iv > 0.f) { np += 1.f; bs += 1.f - iv; }
                bc += fmaxf(s, 0.f) - s * iv + __logf(1.f + __expf(-fabsf(s)));
            }
        }
    } else {
        const int L = (N + NCH - 1) / NCH;
        const int n1 = min(c * L + L, N);
        for (int n = c * L + tid; n < n1; n += 256) {
            float iv = __uint_as_float(it[n]);
            float s = sc[n];
            if (iv > 0.f) { np += 1.f; bs += 1.f - iv; }
            bc += fmaxf(s, 0.f) - s * iv + __logf(1.f + __expf(-fabsf(s)));
        }
    }

    __shared__ float r0[256], r1[256], r2[256];
    __shared__ int s_last;
    r0[tid] = np; r1[tid] = bs; r2[tid] = bc;
    __syncthreads();
    for (int s = 128; s > 0; s >>= 1) {
        if (tid < s) { r0[tid] += r0[tid + s]; r1[tid] += r1[tid + s]; r2[tid] += r2[tid + s]; }
        __syncthreads();
    }
    if (tid == 0) {
        int slot = b * NCH + c;
        g_part2[slot * 3 + 0] = r0[0];
        g_part2[slot * 3 + 1] = r1[0];
        g_part2[slot * 3 + 2] = r2[0];
        __threadfence();
        unsigned int done = atomicAdd(&g_cnt, 1u);
        s_last = (done == (unsigned)(NCH * Bc - 1)) ? 1 : 0;
    }
    __syncthreads();
    if (!s_last) return;

    __shared__ float f0[Bc * NCH], f1[Bc * NCH], f2[Bc * NCH];
    __shared__ float bx[Bc], ob[Bc];
    for (int i = tid; i < Bc * NCH; i += 256) {
        f0[i] = g_part2[i * 3 + 0];
        f1[i] = g_part2[i * 3 + 1];
        f2[i] = g_part2[i * 3 + 2];
    }
    __syncthreads();
    if (tid < Bc) {
        float nps = 0.f, bss = 0.f, bcs = 0.f;
        for (int cc = 0; cc < NCH; cc++) {
            nps += f0[tid * NCH + cc];
            bss += f1[tid * NCH + cc];
            bcs += f2[tid * NCH + cc];
        }
        bx[tid] = (nps > 0.f) ? __fdividef(bss, fmaxf(nps, 1.f)) : 0.f;
        ob[tid] = bcs / (float)N;
    }
    __syncthreads();
    if (tid == 0) {
        float box = 0.f, obj = 0.f;
        for (int bb = 0; bb < Bc; bb++) { box += bx[bb]; obj += ob[bb]; }
        float total = (7.5f * box + 1.0f * obj) / (float)Bc;
        out[0] = total;
        if (out_size > 1) out[1] = box;
        if (out_size > 2) out[2] = obj;
    }
    // Re-zero counters for the next replay (first run uses static zero-init).
    for (int i = tid; i < Bc * Mc; i += 256) g_cnt_m[i] = 0u;
    if (tid == 0) g_cnt = 0u;
}

extern "C" void kernel_launch(void* const* d_in, const int* in_sizes, int n_in,
                              void* d_out, int out_size) {
    const float* boxes   = (const float*)d_in[0];   // [8, 64, N]
    const float* scores  = (const float*)d_in[1];   // [8, N]
    const float* targets = (const float*)d_in[2];   // [8, 64, 4]
    int N = in_sizes[1] / Bc;
    if (N > Nmax) N = Nmax;
    int aligned = ((N & 3) == 0) ? 1 : 0;

    dim3 gd((N + FCH - 1) / FCH, Bc);
    k_dfil<<<gd, 256>>>(boxes, targets, N);
    dim3 gc(Mc, Bc);
    k_ciou<<<gc, 256>>>(targets, N);
    dim3 gr(NCH, Bc);
    k_reduce<<<gr, 256>>>(scores, N, (float*)d_out, out_size, aligned);
}

// round 16
// speedup vs baseline: 1.5684x; 1.5684x over previous
#include <cuda_runtime.h>
#include <cuda_bf16.h>

#define Bc 8
#define Nmax 34000
#define Mc 64
#define EPSL 1e-7f
#define FULLM 0xFFFFFFFFu
#define FCH 256         // anchors per fused block (1 per thread)
#define NCH 48          // reduce chunks per batch
#define SENT 0x8000000000000000ull   // key of +0.0 in high 32; only ciou>0 beats it

// Scratch (static device globals; zero-initialized at load; no allocation allowed)
__device__ float4       g_pb[Bc * Nmax];
__device__ float        g_at1[Bc * Nmax];
__device__ unsigned int g_it[Bc * Nmax];
__device__ float        g_part2[Bc * NCH * 3];
__device__ unsigned int g_cnt;                            // re-zeroed by k_reduce epilogue
__device__ unsigned int g_cnt_m[Bc * Mc];                 // re-zeroed by k_reduce epilogue
__device__ unsigned int g_list[(size_t)Bc * Mc * Nmax];   // survivor anchor indices

// ---------------------------------------------------------------------------
// Fused kernel: DFL decode (1 anchor/thread, scalar coalesced loads, batched
// x[16] per side — R14-proven; the "spill" theory was falsified in R15) +
// mask-screen filter. Grid (ceil(N/FCH), Bc) ~ 1064 blocks.
// Template CN: compile-time N (0 = dynamic) so the 64 load offsets
// (k*16+r)*N become literals -> fewer IMADs in an issue-bound kernel.
// Requires g_cnt_m zeroed on entry (k_reduce epilogue / static init).
// ---------------------------------------------------------------------------
template<int CN>
__global__ __launch_bounds__(256) void k_dfil(const float* __restrict__ boxes,
                                              const float* __restrict__ targets, int Nrt) {
    const int N = (CN > 0) ? CN : Nrt;
    const int b   = blockIdx.y;
    const int c0  = blockIdx.x * FCH;
    const int tid = threadIdx.x;
    const int w   = tid >> 5;

    __shared__ float4 s_t[Mc];
    __shared__ unsigned long long s_mx[16], s_my[16];
    __shared__ int s_wc[8][Mc];    // per-warp counts, then cursors
    __shared__ int s_wb[8][Mc];    // per-warp bases (exclusive prefix)
    __shared__ int s_base[Mc];     // global base per m

    for (int i = tid; i < 8 * Mc; i += 256) s_wc[i >> 6][i & 63] = 0;
    if (tid < 16) { s_mx[tid] = 0ull; s_my[tid] = 0ull; }
    __syncthreads();
    if (tid < Mc) {
        const float* t = targets + ((size_t)b * Mc + tid) * 4;
        float4 tv = make_float4(t[0], t[1], t[2], t[3]);
        s_t[tid] = tv;
        int cx0 = min(max((int)floorf(tv.x), 0), 15);
        int cx1 = min(max((int)floorf(tv.z), 0), 15);
        int cy0 = min(max((int)floorf(tv.y), 0), 15);
        int cy1 = min(max((int)floorf(tv.w), 0), 15);
        unsigned long long bit = 1ull << tid;
        for (int c = cx0; c <= cx1; c++) atomicOr(&s_mx[c], bit);
        for (int c = cy0; c <= cy1; c++) atomicOr(&s_my[c], bit);
    }

    // ---- decode one anchor (batched loads per side -> loads in flight) ----
    const int n = c0 + tid;
    float4 p = make_float4(0.f, 0.f, 0.f, 0.f);
    bool valid = false;

    if (n < N) {
        const float* base = boxes + (size_t)b * 64 * N + n;
        float pb4[4];
#pragma unroll
        for (int k = 0; k < 4; k++) {
            float x[16];                  // batch loads (R14-proven form)
#pragma unroll
            for (int r = 0; r < 16; r++)
                x[r] = base[(size_t)(k * 16 + r) * N];
            float s = 0.f, e = 0.f;
#pragma unroll
            for (int r = 0; r < 16; r++) {
                float t = __expf(x[r]);
                s += t; e += t * (float)r;
            }
            pb4[k] = __fdividef(e, s);
        }
        p = make_float4(pb4[0], pb4[1], pb4[2], pb4[3]);
        size_t o = (size_t)b * N + n;
        g_pb[o]  = p;
        g_at1[o] = atanf(__fdividef(p.z - p.x, p.w - p.y + EPSL));
        g_it[o]  = 0u;
        valid = (p.z > p.x) && (p.w > p.y);
    }
    __syncthreads();   // masks + s_t ready; s_wc zeroed

    // ---- Pass A: screen + count (fire-and-forget smem atomics) ----
    unsigned long long msk = 0ull;
    if (valid) {
        int cx0 = min(max((int)floorf(p.x), 0), 15);
        int cx1 = min(max((int)floorf(p.z), 0), 15);
        int cy0 = min(max((int)floorf(p.y), 0), 15);
        int cy1 = min(max((int)floorf(p.w), 0), 15);
        unsigned long long mx = 0ull, my = 0ull;
        for (int c = cx0; c <= cx1; c++) mx |= s_mx[c];
        for (int c = cy0; c <= cy1; c++) my |= s_my[c];
        unsigned long long cand = mx & my;
        while (cand) {
            int m = __ffsll((long long)cand) - 1;
            cand &= cand - 1;
            float4 t = s_t[m];
            float iw = fminf(p.z, t.z) - fmaxf(p.x, t.x);
            float ih = fminf(p.w, t.w) - fmaxf(p.y, t.y);
            if (iw > 0.f && ih > 0.f) {
                msk |= 1ull << m;
                atomicAdd(&s_wc[w][m], 1);
            }
        }
    }
    __syncthreads();

    // One concurrent batch of global reservations + per-warp prefix bases
    if (tid < Mc) {
        int tot = 0;
#pragma unroll
        for (int ww = 0; ww < 8; ww++) { s_wb[ww][tid] = tot; tot += s_wc[ww][tid]; }
        s_base[tid] = tot ? (int)atomicAdd(&g_cnt_m[b * Mc + tid], (unsigned)tot) : 0;
#pragma unroll
        for (int ww = 0; ww < 8; ww++) s_wc[ww][tid] = 0;   // reset as cursors
    }
    __syncthreads();

    // Pass B: assign slots via per-warp cursors, write indices
    {
        unsigned long long tmp = msk;
        while (tmp) {
            int m = __ffsll((long long)tmp) - 1;
            tmp &= tmp - 1;
            int pos = s_base[m] + s_wb[w][m] + atomicAdd(&s_wc[w][m], 1);
            g_list[(size_t)(b * Mc + m) * Nmax + pos] = (unsigned)n;
        }
    }
}

// ---------------------------------------------------------------------------
// k_ciou: per-(b,m) exact top-10 ciou over the survivor list.
// Sentinel init => insertion only for ciou > 0 (reference keeps topv > 0).
// Extraction: sorted per-thread lists, register offers, shuffle argmax.
// ---------------------------------------------------------------------------
__global__ __launch_bounds__(256) void k_ciou(const float* __restrict__ targets, int N) {
    const int m = blockIdx.x;
    const int b = blockIdx.y;
    const int bm = b * Mc + m;
    const int tid  = threadIdx.x;
    const int lane = tid & 31;
    const int wid  = tid >> 5;

    const float* t = targets + (size_t)bm * 4;
    const float x21 = t[0], y21 = t[1], x22 = t[2], y22 = t[3];
    const float w2 = x22 - x21, h2 = y22 - y21;
    const float area2 = w2 * h2;
    const float at2 = atanf(__fdividef(w2, h2 + EPSL));
    const float sx = x21 + x22, sy = y21 + y22;
    const float VP = 4.0f / (float)(M_PI * M_PI);

    unsigned cnt = g_cnt_m[bm];
    if (cnt > (unsigned)N) cnt = (unsigned)N;

    unsigned long long top[10];
#pragma unroll
    for (int j = 0; j < 10; j++) top[j] = SENT;

    const float4* __restrict__ pb = g_pb + (size_t)b * N;
    const float*  __restrict__ a1 = g_at1 + (size_t)b * N;
    const unsigned* __restrict__ lst = g_list + (size_t)bm * Nmax;

#pragma unroll 4
    for (unsigned i = tid; i < cnt; i += 256) {
        unsigned n = lst[i];
        float4 p = pb[n];
        float at1 = a1[n];
        float w1 = p.z - p.x, h1 = p.w - p.y;

        float iw = fminf(p.z, x22) - fmaxf(p.x, x21); iw = fmaxf(iw, 0.f);
        float ih = fminf(p.w, y22) - fmaxf(p.y, y21); ih = fmaxf(ih, 0.f);
        float inter = iw * ih;
        float uni = w1 * h1 + area2 - inter + EPSL;
        float iou = __fdividef(inter, uni);

        float cw = fmaxf(p.z, x22) - fminf(p.x, x21);
        float ch = fmaxf(p.w, y22) - fminf(p.y, y21);
        float c2 = cw * cw + ch * ch + EPSL;

        float dx = sx - p.x - p.z;
        float dy = sy - p.y - p.w;
        float rho2 = (dx * dx + dy * dy) * 0.25f;

        float d = at2 - at1;
        float v = VP * d * d;
        float av = __fdividef(v * v, v - iou + 1.0f + EPSL);
        float ciou = iou - __fdividef(rho2, c2) - av;

        unsigned u = __float_as_uint(ciou);
        unsigned key = (u & 0x80000000u) ? ~u : (u | 0x80000000u);
        unsigned long long pk =
            ((unsigned long long)key << 32) | (unsigned long long)(0xFFFFFFFFu - n);

        if (pk > top[9]) {   // only ciou > 0 passes (sentinel = +0.0 key)
#pragma unroll
            for (int j = 0; j < 10; j++) {
                if (pk > top[j]) { unsigned long long tmp = top[j]; top[j] = pk; pk = tmp; }
            }
        }
    }

    __shared__ unsigned long long s_w[8];
    __shared__ int                s_wt[8];
    __shared__ unsigned long long s_best;
    __shared__ int                s_btid;

    unsigned long long offer = top[0];

    for (int round = 0; round < 10; ++round) {
        unsigned long long mx = offer; int mt = tid;
#pragma unroll
        for (int off = 16; off > 0; off >>= 1) {
            unsigned long long ov = __shfl_down_sync(FULLM, mx, off);
            int ot = __shfl_down_sync(FULLM, mt, off);
            if (ov > mx) { mx = ov; mt = ot; }
        }
        if (lane == 0) { s_w[wid] = mx; s_wt[wid] = mt; }
        __syncthreads();
        if (wid == 0) {
            unsigned long long v2 = (lane < 8) ? s_w[lane] : 0ull;
            int t2 = (lane < 8) ? s_wt[lane] : 0;
#pragma unroll
            for (int off = 4; off > 0; off >>= 1) {
                unsigned long long ov = __shfl_down_sync(FULLM, v2, off);
                int ot = __shfl_down_sync(FULLM, t2, off);
                if (ov > v2) { v2 = ov; t2 = ot; }
            }
            if (lane == 0) { s_best = v2; s_btid = t2; }
        }
        __syncthreads();
        unsigned long long best = s_best;
        if ((unsigned)(best >> 32) <= 0x80000000u) break;  // value <= 0: done

        if (tid == 0) {
            unsigned n = 0xFFFFFFFFu - (unsigned)(best & 0xFFFFFFFFull);
            atomicMax(&g_it[(size_t)b * N + n], (unsigned)(best >> 32) ^ 0x80000000u);
        }
        if (tid == s_btid) {
#pragma unroll
            for (int j = 0; j < 9; j++) top[j] = top[j + 1];
            top[9] = SENT;
            offer = top[0];
        }
    }
}

// ---------------------------------------------------------------------------
// k_reduce: parallel per-slice reductions (vectorized when N%4==0), grid
// (NCH, Bc). Last block: deterministic fixed-order combine + re-zero counters.
// ---------------------------------------------------------------------------
__global__ __launch_bounds__(256) void k_reduce(const float* __restrict__ scores, int N,
                                                float* out, int out_size, int aligned) {
    const int c = blockIdx.x;
    const int b = blockIdx.y;
    const int tid = threadIdx.x;

    float np = 0.f, bs = 0.f, bc = 0.f;
    const unsigned int* __restrict__ it = g_it + (size_t)b * N;
    const float* __restrict__ sc = scores + (size_t)b * N;

    if (aligned) {
        const int N4 = N >> 2;
        const int L4 = (N4 + NCH - 1) / NCH;
        const int q1 = min(c * L4 + L4, N4);
        for (int q = c * L4 + tid; q < q1; q += 256) {
            uint4  iv4 = *(const uint4*)(it + q * 4);
            float4 s4  = *(const float4*)(sc + q * 4);
            float iv, s;
#pragma unroll
            for (int j = 0; j < 4; j++) {
                iv = __uint_as_float(j == 0 ? iv4.x : j == 1 ? iv4.y : j == 2 ? iv4.z : iv4.w);
                s  = (j == 0 ? s4.x : j == 1 ? s4.y : j == 2 ? s4.z : s4.w);
                if (iv > 0.f) { np += 1.f; bs += 1.f - iv; }
                bc += fmaxf(s, 0.f) - s * iv + __logf(1.f + __expf(-fabsf(s)));
            }
        }
    } else {
        const int L = (N + NCH - 1) / NCH;
        const int n1 = min(c * L + L, N);
        for (int n = c * L + tid; n < n1; n += 256) {
            float iv = __uint_as_float(it[n]);
            float s = sc[n];
            if (iv > 0.f) { np += 1.f; bs += 1.f - iv; }
            bc += fmaxf(s, 0.f) - s * iv + __logf(1.f + __expf(-fabsf(s)));
        }
    }

    __shared__ float r0[256], r1[256], r2[256];
    __shared__ int s_last;
    r0[tid] = np; r1[tid] = bs; r2[tid] = bc;
    __syncthreads();
    for (int s = 128; s > 0; s >>= 1) {
        if (tid < s) { r0[tid] += r0[tid + s]; r1[tid] += r1[tid + s]; r2[tid] += r2[tid + s]; }
        __syncthreads();
    }
    if (tid == 0) {
        int slot = b * NCH + c;
        g_part2[slot * 3 + 0] = r0[0];
        g_part2[slot * 3 + 1] = r1[0];
        g_part2[slot * 3 + 2] = r2[0];
        __threadfence();
        unsigned int done = atomicAdd(&g_cnt, 1u);
        s_last = (done == (unsigned)(NCH * Bc - 1)) ? 1 : 0;
    }
    __syncthreads();
    if (!s_last) return;

    __shared__ float f0[Bc * NCH], f1[Bc * NCH], f2[Bc * NCH];
    __shared__ float bx[Bc], ob[Bc];
    for (int i = tid; i < Bc * NCH; i += 256) {
        f0[i] = g_part2[i * 3 + 0];
        f1[i] = g_part2[i * 3 + 1];
        f2[i] = g_part2[i * 3 + 2];
    }
    __syncthreads();
    if (tid < Bc) {
        float nps = 0.f, bss = 0.f, bcs = 0.f;
        for (int cc = 0; cc < NCH; cc++) {
            nps += f0[tid * NCH + cc];
            bss += f1[tid * NCH + cc];
            bcs += f2[tid * NCH + cc];
        }
        bx[tid] = (nps > 0.f) ? __fdividef(bss, fmaxf(nps, 1.f)) : 0.f;
        ob[tid] = bcs / (float)N;
    }
    __syncthreads();
    if (tid == 0) {
        float box = 0.f, obj = 0.f;
        for (int bb = 0; bb < Bc; bb++) { box += bx[bb]; obj += ob[bb]; }
        float total = (7.5f * box + 1.0f * obj) / (float)Bc;
        out[0] = total;
        if (out_size > 1) out[1] = box;
        if (out_size > 2) out[2] = obj;
    }
    // Re-zero counters for the next replay (first run uses static zero-init).
    for (int i = tid; i < Bc * Mc; i += 256) g_cnt_m[i] = 0u;
    if (tid == 0) g_cnt = 0u;
}

extern "C" void kernel_launch(void* const* d_in, const int* in_sizes, int n_in,
                              void* d_out, int out_size) {
    const float* boxes   = (const float*)d_in[0];   // [8, 64, N]
    const float* scores  = (const float*)d_in[1];   // [8, N]
    const float* targets = (const float*)d_in[2];   // [8, 64, 4]
    int N = in_sizes[1] / Bc;
    if (N > Nmax) N = Nmax;
    int aligned = ((N & 3) == 0) ? 1 : 0;

    dim3 gd((N + FCH - 1) / FCH, Bc);
    if (N == 34000) k_dfil<34000><<<gd, 256>>>(boxes, targets, N);
    else            k_dfil<0>    <<<gd, 256>>>(boxes, targets, N);
    dim3 gc(Mc, Bc);
    k_ciou<<<gc, 256>>>(targets, N);
    dim3 gr(NCH, Bc);
    k_reduce<<<gr, 256>>>(scores, N, (float*)d_out, out_size, aligned);
}

// round 17
// speedup vs baseline: 1.5787x; 1.0065x over previous
#include <cuda_runtime.h>
#include <cuda_bf16.h>

#define Bc 8
#define Nmax 34000
#define Mc 64
#define EPSL 1e-7f
#define FULLM 0xFFFFFFFFu
#define FCH 256         // anchors per fused block (1 per thread)
#define NCH 48          // reduce chunks per batch
#define SENT 0x8000000000000000ull   // key of +0.0 in high 32; only ciou>0 beats it

// Scratch (static device globals; zero-initialized at load; no allocation allowed)
__device__ float4       g_pb[Bc * Nmax];
__device__ float        g_at1[Bc * Nmax];
__device__ unsigned int g_it[Bc * Nmax];
__device__ float        g_part2[Bc * NCH * 3];
__device__ unsigned int g_cnt;                            // re-zeroed by k_reduce epilogue
__device__ unsigned int g_cnt_m[Bc * Mc];                 // re-zeroed by k_reduce epilogue
__device__ unsigned int g_list[(size_t)Bc * Mc * Nmax];   // survivor anchor indices

// ---------------------------------------------------------------------------
// Fused kernel: DFL decode (1 anchor/thread, batched x[16] loads) +
// mask-screen filter. Template CN = compile-time N.
// R17: pointer re-based to channel 32 so ALL 64 load byte-offsets
// (k*16+r-32)*CN*4 fall in +/-4.35MB -> inside LDG's imm24 window ->
// single-instruction loads, no per-load address ALU.
// Requires g_cnt_m zeroed on entry (k_reduce epilogue / static init).
// ---------------------------------------------------------------------------
template<int CN>
__global__ __launch_bounds__(256) void k_dfil(const float* __restrict__ boxes,
                                              const float* __restrict__ targets, int Nrt) {
    const int N = (CN > 0) ? CN : Nrt;
    const int b   = blockIdx.y;
    const int c0  = blockIdx.x * FCH;
    const int tid = threadIdx.x;
    const int w   = tid >> 5;

    __shared__ float4 s_t[Mc];
    __shared__ unsigned long long s_mx[16], s_my[16];
    __shared__ int s_wc[8][Mc];    // per-warp counts, then cursors
    __shared__ int s_wb[8][Mc];    // per-warp bases (exclusive prefix)
    __shared__ int s_base[Mc];     // global base per m

    for (int i = tid; i < 8 * Mc; i += 256) s_wc[i >> 6][i & 63] = 0;
    if (tid < 16) { s_mx[tid] = 0ull; s_my[tid] = 0ull; }
    __syncthreads();
    if (tid < Mc) {
        const float* t = targets + ((size_t)b * Mc + tid) * 4;
        float4 tv = make_float4(t[0], t[1], t[2], t[3]);
        s_t[tid] = tv;
        int cx0 = min(max((int)floorf(tv.x), 0), 15);
        int cx1 = min(max((int)floorf(tv.z), 0), 15);
        int cy0 = min(max((int)floorf(tv.y), 0), 15);
        int cy1 = min(max((int)floorf(tv.w), 0), 15);
        unsigned long long bit = 1ull << tid;
        for (int c = cx0; c <= cx1; c++) atomicOr(&s_mx[c], bit);
        for (int c = cy0; c <= cy1; c++) atomicOr(&s_my[c], bit);
    }

    // ---- decode one anchor (batched loads; mid-slab base for imm offsets) ----
    const int n = c0 + tid;
    float4 p = make_float4(0.f, 0.f, 0.f, 0.f);
    bool valid = false;

    if (n < N) {
        // base at channel 32: offsets (k*16+r-32)*N span [-32N, +31N] elements
        const float* base = boxes + ((size_t)b * 64 + 32) * N + n;
        float pb4[4];
#pragma unroll
        for (int k = 0; k < 4; k++) {
            float x[16];
#pragma unroll
            for (int r = 0; r < 16; r++)
                x[r] = base[(k * 16 + r - 32) * N];   // int const * template N -> imm
            float s = 0.f, e = 0.f;
#pragma unroll
            for (int r = 0; r < 16; r++) {
                float t = __expf(x[r]);
                s += t; e += t * (float)r;
            }
            pb4[k] = __fdividef(e, s);
        }
        p = make_float4(pb4[0], pb4[1], pb4[2], pb4[3]);
        size_t o = (size_t)b * N + n;
        g_pb[o]  = p;
        g_at1[o] = atanf(__fdividef(p.z - p.x, p.w - p.y + EPSL));
        g_it[o]  = 0u;
        valid = (p.z > p.x) && (p.w > p.y);
    }
    __syncthreads();   // masks + s_t ready; s_wc zeroed

    // ---- Pass A: screen + count (fire-and-forget smem atomics) ----
    unsigned long long msk = 0ull;
    if (valid) {
        int cx0 = min(max((int)floorf(p.x), 0), 15);
        int cx1 = min(max((int)floorf(p.z), 0), 15);
        int cy0 = min(max((int)floorf(p.y), 0), 15);
        int cy1 = min(max((int)floorf(p.w), 0), 15);
        unsigned long long mx = 0ull, my = 0ull;
        for (int c = cx0; c <= cx1; c++) mx |= s_mx[c];
        for (int c = cy0; c <= cy1; c++) my |= s_my[c];
        unsigned long long cand = mx & my;
        while (cand) {
            int m = __ffsll((long long)cand) - 1;
            cand &= cand - 1;
            float4 t = s_t[m];
            float iw = fminf(p.z, t.z) - fmaxf(p.x, t.x);
            float ih = fminf(p.w, t.w) - fmaxf(p.y, t.y);
            if (iw > 0.f && ih > 0.f) {
                msk |= 1ull << m;
                atomicAdd(&s_wc[w][m], 1);
            }
        }
    }
    __syncthreads();

    // One concurrent batch of global reservations + per-warp prefix bases
    if (tid < Mc) {
        int tot = 0;
#pragma unroll
        for (int ww = 0; ww < 8; ww++) { s_wb[ww][tid] = tot; tot += s_wc[ww][tid]; }
        s_base[tid] = tot ? (int)atomicAdd(&g_cnt_m[b * Mc + tid], (unsigned)tot) : 0;
#pragma unroll
        for (int ww = 0; ww < 8; ww++) s_wc[ww][tid] = 0;   // reset as cursors
    }
    __syncthreads();

    // Pass B: assign slots via per-warp cursors, write indices
    {
        unsigned long long tmp = msk;
        while (tmp) {
            int m = __ffsll((long long)tmp) - 1;
            tmp &= tmp - 1;
            int pos = s_base[m] + s_wb[w][m] + atomicAdd(&s_wc[w][m], 1);
            g_list[(size_t)(b * Mc + m) * Nmax + pos] = (unsigned)n;
        }
    }
}

// ---------------------------------------------------------------------------
// k_ciou: per-(b,m) exact top-10 ciou over the survivor list (unchanged).
// ---------------------------------------------------------------------------
__global__ __launch_bounds__(256) void k_ciou(const float* __restrict__ targets, int N) {
    const int m = blockIdx.x;
    const int b = blockIdx.y;
    const int bm = b * Mc + m;
    const int tid  = threadIdx.x;
    const int lane = tid & 31;
    const int wid  = tid >> 5;

    const float* t = targets + (size_t)bm * 4;
    const float x21 = t[0], y21 = t[1], x22 = t[2], y22 = t[3];
    const float w2 = x22 - x21, h2 = y22 - y21;
    const float area2 = w2 * h2;
    const float at2 = atanf(__fdividef(w2, h2 + EPSL));
    const float sx = x21 + x22, sy = y21 + y22;
    const float VP = 4.0f / (float)(M_PI * M_PI);

    unsigned cnt = g_cnt_m[bm];
    if (cnt > (unsigned)N) cnt = (unsigned)N;

    unsigned long long top[10];
#pragma unroll
    for (int j = 0; j < 10; j++) top[j] = SENT;

    const float4* __restrict__ pb = g_pb + (size_t)b * N;
    const float*  __restrict__ a1 = g_at1 + (size_t)b * N;
    const unsigned* __restrict__ lst = g_list + (size_t)bm * Nmax;

#pragma unroll 4
    for (unsigned i = tid; i < cnt; i += 256) {
        unsigned n = lst[i];
        float4 p = pb[n];
        float at1 = a1[n];
        float w1 = p.z - p.x, h1 = p.w - p.y;

        float iw = fminf(p.z, x22) - fmaxf(p.x, x21); iw = fmaxf(iw, 0.f);
        float ih = fminf(p.w, y22) - fmaxf(p.y, y21); ih = fmaxf(ih, 0.f);
        float inter = iw * ih;
        float uni = w1 * h1 + area2 - inter + EPSL;
        float iou = __fdividef(inter, uni);

        float cw = fmaxf(p.z, x22) - fminf(p.x, x21);
        float ch = fmaxf(p.w, y22) - fminf(p.y, y21);
        float c2 = cw * cw + ch * ch + EPSL;

        float dx = sx - p.x - p.z;
        float dy = sy - p.y - p.w;
        float rho2 = (dx * dx + dy * dy) * 0.25f;

        float d = at2 - at1;
        float v = VP * d * d;
        float av = __fdividef(v * v, v - iou + 1.0f + EPSL);
        float ciou = iou - __fdividef(rho2, c2) - av;

        unsigned u = __float_as_uint(ciou);
        unsigned key = (u & 0x80000000u) ? ~u : (u | 0x80000000u);
        unsigned long long pk =
            ((unsigned long long)key << 32) | (unsigned long long)(0xFFFFFFFFu - n);

        if (pk > top[9]) {   // only ciou > 0 passes (sentinel = +0.0 key)
#pragma unroll
            for (int j = 0; j < 10; j++) {
                if (pk > top[j]) { unsigned long long tmp = top[j]; top[j] = pk; pk = tmp; }
            }
        }
    }

    __shared__ unsigned long long s_w[8];
    __shared__ int                s_wt[8];
    __shared__ unsigned long long s_best;
    __shared__ int                s_btid;

    unsigned long long offer = top[0];

    for (int round = 0; round < 10; ++round) {
        unsigned long long mx = offer; int mt = tid;
#pragma unroll
        for (int off = 16; off > 0; off >>= 1) {
            unsigned long long ov = __shfl_down_sync(FULLM, mx, off);
            int ot = __shfl_down_sync(FULLM, mt, off);
            if (ov > mx) { mx = ov; mt = ot; }
        }
        if (lane == 0) { s_w[wid] = mx; s_wt[wid] = mt; }
        __syncthreads();
        if (wid == 0) {
            unsigned long long v2 = (lane < 8) ? s_w[lane] : 0ull;
            int t2 = (lane < 8) ? s_wt[lane] : 0;
#pragma unroll
            for (int off = 4; off > 0; off >>= 1) {
                unsigned long long ov = __shfl_down_sync(FULLM, v2, off);
                int ot = __shfl_down_sync(FULLM, t2, off);
                if (ov > v2) { v2 = ov; t2 = ot; }
            }
            if (lane == 0) { s_best = v2; s_btid = t2; }
        }
        __syncthreads();
        unsigned long long best = s_best;
        if ((unsigned)(best >> 32) <= 0x80000000u) break;  // value <= 0: done

        if (tid == 0) {
            unsigned n = 0xFFFFFFFFu - (unsigned)(best & 0xFFFFFFFFull);
            atomicMax(&g_it[(size_t)b * N + n], (unsigned)(best >> 32) ^ 0x80000000u);
        }
        if (tid == s_btid) {
#pragma unroll
            for (int j = 0; j < 9; j++) top[j] = top[j + 1];
            top[9] = SENT;
            offer = top[0];
        }
    }
}

// ---------------------------------------------------------------------------
// k_reduce: parallel per-slice reductions (vectorized when N%4==0), grid
// (NCH, Bc). Last block: deterministic fixed-order combine + re-zero counters.
// ---------------------------------------------------------------------------
__global__ __launch_bounds__(256) void k_reduce(const float* __restrict__ scores, int N,
                                                float* out, int out_size, int aligned) {
    const int c = blockIdx.x;
    const int b = blockIdx.y;
    const int tid = threadIdx.x;

    float np = 0.f, bs = 0.f, bc = 0.f;
    const unsigned int* __restrict__ it = g_it + (size_t)b * N;
    const float* __restrict__ sc = scores + (size_t)b * N;

    if (aligned) {
        const int N4 = N >> 2;
        const int L4 = (N4 + NCH - 1) / NCH;
        const int q1 = min(c * L4 + L4, N4);
        for (int q = c * L4 + tid; q < q1; q += 256) {
            uint4  iv4 = *(const uint4*)(it + q * 4);
            float4 s4  = *(const float4*)(sc + q * 4);
            float iv, s;
#pragma unroll
            for (int j = 0; j < 4; j++) {
                iv = __uint_as_float(j == 0 ? iv4.x : j == 1 ? iv4.y : j == 2 ? iv4.z : iv4.w);
                s  = (j == 0 ? s4.x : j == 1 ? s4.y : j == 2 ? s4.z : s4.w);
                if (iv > 0.f) { np += 1.f; bs += 1.f - iv; }
                bc += fmaxf(s, 0.f) - s * iv + __logf(1.f + __expf(-fabsf(s)));
            }
        }
    } else {
        const int L = (N + NCH - 1) / NCH;
        const int n1 = min(c * L + L, N);
        for (int n = c * L + tid; n < n1; n += 256) {
            float iv = __uint_as_float(it[n]);
            float s = sc[n];
            if (iv > 0.f) { np += 1.f; bs += 1.f - iv; }
            bc += fmaxf(s, 0.f) - s * iv + __logf(1.f + __expf(-fabsf(s)));
        }
    }

    __shared__ float r0[256], r1[256], r2[256];
    __shared__ int s_last;
    r0[tid] = np; r1[tid] = bs; r2[tid] = bc;
    __syncthreads();
    for (int s = 128; s > 0; s >>= 1) {
        if (tid < s) { r0[tid] += r0[tid + s]; r1[tid] += r1[tid + s]; r2[tid] += r2[tid + s]; }
        __syncthreads();
    }
    if (tid == 0) {
        int slot = b * NCH + c;
        g_part2[slot * 3 + 0] = r0[0];
        g_part2[slot * 3 + 1] = r1[0];
        g_part2[slot * 3 + 2] = r2[0];
        __threadfence();
        unsigned int done = atomicAdd(&g_cnt, 1u);
        s_last = (done == (unsigned)(NCH * Bc - 1)) ? 1 : 0;
    }
    __syncthreads();
    if (!s_last) return;

    __shared__ float f0[Bc * NCH], f1[Bc * NCH], f2[Bc * NCH];
    __shared__ float bx[Bc], ob[Bc];
    for (int i = tid; i < Bc * NCH; i += 256) {
        f0[i] = g_part2[i * 3 + 0];
        f1[i] = g_part2[i * 3 + 1];
        f2[i] = g_part2[i * 3 + 2];
    }
    __syncthreads();
    if (tid < Bc) {
        float nps = 0.f, bss = 0.f, bcs = 0.f;
        for (int cc = 0; cc < NCH; cc++) {
            nps += f0[tid * NCH + cc];
            bss += f1[tid * NCH + cc];
            bcs += f2[tid * NCH + cc];
        }
        bx[tid] = (nps > 0.f) ? __fdividef(bss, fmaxf(nps, 1.f)) : 0.f;
        ob[tid] = bcs / (float)N;
    }
    __syncthreads();
    if (tid == 0) {
        float box = 0.f, obj = 0.f;
        for (int bb = 0; bb < Bc; bb++) { box += bx[bb]; obj += ob[bb]; }
        float total = (7.5f * box + 1.0f * obj) / (float)Bc;
        out[0] = total;
        if (out_size > 1) out[1] = box;
        if (out_size > 2) out[2] = obj;
    }
    // Re-zero counters for the next replay (first run uses static zero-init).
    for (int i = tid; i < Bc * Mc; i += 256) g_cnt_m[i] = 0u;
    if (tid == 0) g_cnt = 0u;
}

extern "C" void kernel_launch(void* const* d_in, const int* in_sizes, int n_in,
                              void* d_out, int out_size) {
    const float* boxes   = (const float*)d_in[0];   // [8, 64, N]
    const float* scores  = (const float*)d_in[1];   // [8, N]
    const float* targets = (const float*)d_in[2];   // [8, 64, 4]
    int N = in_sizes[1] / Bc;
    if (N > Nmax) N = Nmax;
    int aligned = ((N & 3) == 0) ? 1 : 0;

    dim3 gd((N + FCH - 1) / FCH, Bc);
    if (N == 34000) k_dfil<34000><<<gd, 256>>>(boxes, targets, N);
    else            k_dfil<0>    <<<gd, 256>>>(boxes, targets, N);
    dim3 gc(Mc, Bc);
    k_ciou<<<gc, 256>>>(targets, N);
    dim3 gr(NCH, Bc);
    k_reduce<<<gr, 256>>>(scores, N, (float*)d_out, out_size, aligned);
}